// round 1
// baseline (speedup 1.0000x reference)
#include <cuda_runtime.h>

#define L   768
#define D   256
#define NT  12
#define SPAN 8

// ---------------- device scratch (static, no allocs) ----------------
__device__ __align__(16) float g_ht[8][L * D];        // ht per span-length diagonal
__device__ __align__(16) float g_z[L * 4 * D];        // z buffer (1024 cols)
__device__ __align__(16) float g_tagsc[8][L * NT];    // tag scores per diagonal
__device__ __align__(16) float g_xs[L * NT * SPAN];   // gathered span scores [i][t2][k]

// ---------------- GEMM for h = feats @ Wd^T + bd ----------------
// M=768, N=256, K=512. BM=128, BN=64, BK=16, TM=8, TN=4, 256 threads.
__global__ void sgemm_h(const float* __restrict__ A, const float* __restrict__ B,
                        const float* __restrict__ bias)
{
    __shared__ float As[16][128];
    __shared__ float Bs[16][64];
    const int K = 512, N = 256;
    int tid = threadIdx.x;
    int tx = tid & 15, ty = tid >> 4;
    int m0 = blockIdx.y * 128, n0 = blockIdx.x * 64;
    float acc[8][4] = {};
    for (int k0 = 0; k0 < K; k0 += 16) {
#pragma unroll
        for (int it = 0; it < 2; it++) {
            int idx = tid + it * 256;
            int r = idx >> 2, c = (idx & 3) << 2;
            float4 v = *(const float4*)&A[(size_t)(m0 + r) * K + k0 + c];
            As[c][r] = v.x; As[c+1][r] = v.y; As[c+2][r] = v.z; As[c+3][r] = v.w;
        }
        {
            int r = tid >> 2, c = (tid & 3) << 2;
            float4 v = *(const float4*)&B[(size_t)(n0 + r) * K + k0 + c];
            Bs[c][r] = v.x; Bs[c+1][r] = v.y; Bs[c+2][r] = v.z; Bs[c+3][r] = v.w;
        }
        __syncthreads();
#pragma unroll
        for (int k = 0; k < 16; k++) {
            float4 a0 = *(const float4*)&As[k][ty * 8];
            float4 a1 = *(const float4*)&As[k][ty * 8 + 4];
            float4 b0 = *(const float4*)&Bs[k][tx * 4];
            float av[8] = {a0.x,a0.y,a0.z,a0.w,a1.x,a1.y,a1.z,a1.w};
            float bv[4] = {b0.x,b0.y,b0.z,b0.w};
#pragma unroll
            for (int i = 0; i < 8; i++)
#pragma unroll
                for (int j = 0; j < 4; j++)
                    acc[i][j] = fmaf(av[i], bv[j], acc[i][j]);
        }
        __syncthreads();
    }
#pragma unroll
    for (int i = 0; i < 8; i++) {
        int m = m0 + ty * 8 + i;
#pragma unroll
        for (int j = 0; j < 4; j++) {
            int n = n0 + tx * 4 + j;
            g_ht[0][(size_t)m * N + n] = acc[i][j] + bias[n];
        }
    }
}

// ---------------- dual GEMM: z = l@WL^T + r@WR^T (+bias in epilogue) ----------------
// l = ht_prev[m], r = ht_prev[m+1]. N=1024 (cols <256 -> Wl/Wr; >=256 -> Gl/Gr).
// M = 768 - sl.  Shared A tile carries BM+1=129 rows so l/r share one load.
__global__ void sgemm_dual(const float* __restrict__ Wl, const float* __restrict__ Wr,
                           const float* __restrict__ Gl, const float* __restrict__ Gr,
                           const float* __restrict__ bl, const float* __restrict__ br,
                           const float* __restrict__ bgl, const float* __restrict__ bgr,
                           int sl)
{
    const int M = L - sl;                 // output rows; A rows 0..M valid
    const float* Aht = g_ht[sl - 1];
    __shared__ float As[16][132];         // 129 used, stride 132 keeps 16B align
    __shared__ float BsL[16][64];
    __shared__ float BsR[16][64];
    int tid = threadIdx.x;
    int tx = tid & 15, ty = tid >> 4;
    int m0 = blockIdx.y * 128, n0 = blockIdx.x * 64;
    const float* BLg = (n0 < 256) ? (Wl + (size_t)n0 * 256) : (Gl + (size_t)(n0 - 256) * 256);
    const float* BRg = (n0 < 256) ? (Wr + (size_t)n0 * 256) : (Gr + (size_t)(n0 - 256) * 256);
    float acc[8][4] = {};
    for (int k0 = 0; k0 < 256; k0 += 16) {
#pragma unroll
        for (int it = 0; it < 2; it++) {
            int idx = tid + it * 256;
            int r = idx >> 2, c = (idx & 3) << 2;
            int gm = m0 + r;
            float4 v = (gm <= M) ? *(const float4*)&Aht[(size_t)gm * 256 + k0 + c]
                                 : make_float4(0.f, 0.f, 0.f, 0.f);
            As[c][r] = v.x; As[c+1][r] = v.y; As[c+2][r] = v.z; As[c+3][r] = v.w;
        }
        if (tid < 4) {                    // extra row 128 (for r of last row)
            int c = tid << 2;
            int gm = m0 + 128;
            float4 v = (gm <= M) ? *(const float4*)&Aht[(size_t)gm * 256 + k0 + c]
                                 : make_float4(0.f, 0.f, 0.f, 0.f);
            As[c][128] = v.x; As[c+1][128] = v.y; As[c+2][128] = v.z; As[c+3][128] = v.w;
        }
        {
            int r = tid >> 2, c = (tid & 3) << 2;
            float4 v = *(const float4*)&BLg[(size_t)r * 256 + k0 + c];
            BsL[c][r] = v.x; BsL[c+1][r] = v.y; BsL[c+2][r] = v.z; BsL[c+3][r] = v.w;
            float4 w = *(const float4*)&BRg[(size_t)r * 256 + k0 + c];
            BsR[c][r] = w.x; BsR[c+1][r] = w.y; BsR[c+2][r] = w.z; BsR[c+3][r] = w.w;
        }
        __syncthreads();
#pragma unroll
        for (int k = 0; k < 16; k++) {
            const float* ap = &As[k][ty * 8];
            float4 a0 = *(const float4*)ap;
            float4 a1 = *(const float4*)(ap + 4);
            float ax = ap[8];
            float al[8] = {a0.x,a0.y,a0.z,a0.w,a1.x,a1.y,a1.z,a1.w};
            float ar[8] = {a0.y,a0.z,a0.w,a1.x,a1.y,a1.z,a1.w,ax};
            float4 b0 = *(const float4*)&BsL[k][tx * 4];
            float4 b1 = *(const float4*)&BsR[k][tx * 4];
            float bL[4] = {b0.x,b0.y,b0.z,b0.w};
            float bR[4] = {b1.x,b1.y,b1.z,b1.w};
#pragma unroll
            for (int i = 0; i < 8; i++)
#pragma unroll
                for (int j = 0; j < 4; j++)
                    acc[i][j] = fmaf(ar[i], bR[j], fmaf(al[i], bL[j], acc[i][j]));
        }
        __syncthreads();
    }
    float biasv[4];
#pragma unroll
    for (int j = 0; j < 4; j++) {
        int n = n0 + tx * 4 + j;
        biasv[j] = (n < 256) ? (bl[n] + br[n]) : (bgl[n - 256] + bgr[n - 256]);
    }
#pragma unroll
    for (int i = 0; i < 8; i++) {
        int m = m0 + ty * 8 + i;
        if (m < M) {
#pragma unroll
            for (int j = 0; j < 4; j++)
                g_z[(size_t)m * 1024 + n0 + tx * 4 + j] = acc[i][j] + biasv[j];
        }
    }
}

// ---------------- gate epilogue: ht_sl = w0*h_hat + w1*l + w2*r ----------------
__global__ void gate_kernel(int sl)
{
    const int M = L - sl;
    int idx = blockIdx.x * 256 + threadIdx.x;
    if (idx >= M * D) return;
    int pos = idx >> 8;
    int d = idx & 255;
    const float* zp = g_z + (size_t)pos * 1024;
    float hv = zp[d];
    float g0 = zp[256 + d], g1 = zp[512 + d], g2 = zp[768 + d];
    float hh = 4.f / (1.f + __expf(-hv)) - 2.f;
    float mx = fmaxf(g0, fmaxf(g1, g2));
    float e0 = __expf(g0 - mx), e1 = __expf(g1 - mx), e2 = __expf(g2 - mx);
    float inv = 1.f / (e0 + e1 + e2);
    float lft = g_ht[sl - 1][idx];
    float rgt = g_ht[sl - 1][idx + D];
    g_ht[sl][idx] = (e0 * hh + e1 * lft + e2 * rgt) * inv;
}

// ---------------- init xs to -1e30 (invalid span starts) ----------------
__global__ void init_xs()
{
    int idx = blockIdx.x * 256 + threadIdx.x;
    if (idx < L * NT * SPAN) g_xs[idx] = -1e30f;
}

// ---------------- tag scores + gather into xs layout ----------------
// warp per (sl,pos): tagsc[sl][pos][t] = ht_sl[pos]·Wt[t] + bt[t]
// also writes xs[i=pos+sl][t][k=7-sl]
__global__ void tagsc_kernel(const float* __restrict__ Wt, const float* __restrict__ bt)
{
    __shared__ float sWt[NT * D];
    int tid = threadIdx.x;
    for (int i = tid; i < NT * D; i += 256) sWt[i] = Wt[i];
    __syncthreads();
    int warp = tid >> 5, lane = tid & 31;
    int gw = blockIdx.x * 8 + warp;        // 0..6143
    int sl = gw / L;
    int pos = gw - sl * L;
    if (pos + sl >= L) return;
    const float* hp = g_ht[sl] + (size_t)pos * D;
    float4 h0 = *(const float4*)&hp[lane * 8];
    float4 h1 = *(const float4*)&hp[lane * 8 + 4];
    float hv[8] = {h0.x,h0.y,h0.z,h0.w,h1.x,h1.y,h1.z,h1.w};
    int i_end = pos + sl, k = 7 - sl;
#pragma unroll
    for (int t = 0; t < NT; t++) {
        const float* wp = &sWt[t * D + lane * 8];
        float4 w0 = *(const float4*)wp;
        float4 w1 = *(const float4*)(wp + 4);
        float s = hv[0]*w0.x + hv[1]*w0.y + hv[2]*w0.z + hv[3]*w0.w
                + hv[4]*w1.x + hv[5]*w1.y + hv[6]*w1.z + hv[7]*w1.w;
#pragma unroll
        for (int o = 16; o; o >>= 1) s += __shfl_xor_sync(0xffffffffu, s, o);
        if (lane == 0) {
            float val = s + bt[t];
            g_tagsc[sl][pos * NT + t] = val;
            g_xs[((size_t)i_end * NT + t) * SPAN + k] = val;
        }
    }
}

// ---------------- gold score + sequential forward scan ----------------
// single warp; lanes 0..11 = tag t2. beta_j[t2] = LSE_t1(trans[t1][t2]+alpha_j[t1])
// computed via exp(trans) matvec; alpha_i[t2] = LSE_k(xs[i][t2][k] + beta_{i-8+k}[t2]).
__global__ void forward_kernel(const float* __restrict__ trans,
                               const float* __restrict__ bt,
                               const int* __restrict__ tags,
                               float* __restrict__ out)
{
    const int lane = threadIdx.x;

    // ---- gold score (96 spans) ----
    float gold = 0.f;
    for (int s = lane; s < 96; s += 32) {
        int i  = tags[s * 4 + 0];
        int j  = tags[s * 4 + 1];
        int pr = tags[s * 4 + 2];
        int t  = tags[s * 4 + 3];
        int sl = j - i;
        float base;
        if (sl >= 0 && sl < SPAN && i >= 0 && i + sl < L)
            base = g_tagsc[sl][i * NT + t];
        else
            base = bt[t];                  // zero-score region: tagsc = bt
        gold += base + trans[pr * NT + t];
    }
#pragma unroll
    for (int o = 16; o; o >>= 1) gold += __shfl_xor_sync(0xffffffffu, gold, o);

    // ---- setup ----
    __shared__ float beta[8][NT];
    __shared__ float a_sh[NT];
    const bool act = lane < NT;
    const int t2 = lane;
    float Texp[NT];
    if (act) {
#pragma unroll
        for (int t1 = 0; t1 < NT; t1++) Texp[t1] = __expf(trans[t1 * NT + t2]);
        // beta_{-1}: alpha_{-1} = {START_ID=10: 0, else -10000}
        float m = -1e30f;
        float v[NT];
#pragma unroll
        for (int t1 = 0; t1 < NT; t1++) {
            v[t1] = trans[t1 * NT + t2] + (t1 == 10 ? 0.f : -10000.f);
            m = fmaxf(m, v[t1]);
        }
        float s = 0.f;
#pragma unroll
        for (int t1 = 0; t1 < NT; t1++) s += __expf(v[t1] - m);
        beta[7][t2] = m + __logf(s);       // slot for j=-1 is (-1)&7 = 7
#pragma unroll
        for (int k = 0; k < 7; k++) beta[k][t2] = 0.f;  // only paired with xs=-1e30
    }
    __syncwarp();

    // ---- scan ----
    float4 xA = make_float4(0.f,0.f,0.f,0.f), xB = xA;
    if (act) {
        const float4* xp = (const float4*)&g_xs[(size_t)t2 * SPAN];
        xA = xp[0]; xB = xp[1];
    }
    float alpha = -1e30f;
    for (int i = 0; i < L; i++) {
        float4 cA = xA, cB = xB;
        if (act && i + 1 < L) {            // prefetch next step
            const float4* xp = (const float4*)&g_xs[((size_t)(i + 1) * NT + t2) * SPAN];
            xA = xp[0]; xB = xp[1];
        }
        if (act) {
            float v[8] = {cA.x,cA.y,cA.z,cA.w,cB.x,cB.y,cB.z,cB.w};
            float m = -1e30f;
#pragma unroll
            for (int k = 0; k < 8; k++) {  // beta_{i-8+k} lives in slot (i+k)&7
                v[k] += beta[(i + k) & 7][t2];
                m = fmaxf(m, v[k]);
            }
            float s = 0.f;
#pragma unroll
            for (int k = 0; k < 8; k++) s += __expf(v[k] - m);
            alpha = m + __logf(s);
        }
        float shift = __shfl_sync(0xffffffffu, alpha, 0);
        float a = act ? __expf(alpha - shift) : 0.f;
        __syncwarp();                      // prev iter's a_sh reads done
        if (act) a_sh[t2] = a;
        __syncwarp();
        if (act) {
            float ss = 0.f;
#pragma unroll
            for (int t1 = 0; t1 < NT; t1++) ss = fmaf(Texp[t1], a_sh[t1], ss);
            beta[i & 7][t2] = shift + __logf(ss);   // own column: no cross-lane hazard
        }
    }
    __syncwarp();
    if (act) a_sh[t2] = alpha;             // alpha_{L-1}
    __syncwarp();
    if (lane == 0) {
        float logZ = 0.f;
#pragma unroll
        for (int t = 0; t < 11; t++) logZ += a_sh[t];   // :STOP_ID = tags 0..10
        out[0] = logZ - gold;
    }
}

// ---------------- launch ----------------
extern "C" void kernel_launch(void* const* d_in, const int* in_sizes, int n_in,
                              void* d_out, int out_size)
{
    const float* feats = (const float*)d_in[0];
    const int*   tags  = (const int*)d_in[1];
    const float* Wd    = (const float*)d_in[2];
    const float* bd    = (const float*)d_in[3];
    const float* Wl    = (const float*)d_in[4];
    const float* bl    = (const float*)d_in[5];
    const float* Wr    = (const float*)d_in[6];
    const float* br    = (const float*)d_in[7];
    const float* Gl    = (const float*)d_in[8];
    const float* bgl   = (const float*)d_in[9];
    const float* Gr    = (const float*)d_in[10];
    const float* bgr   = (const float*)d_in[11];
    const float* Wt    = (const float*)d_in[12];
    const float* bt    = (const float*)d_in[13];
    const float* trans = (const float*)d_in[14];
    float* out = (float*)d_out;

    // h = feats @ Wd^T + bd
    sgemm_h<<<dim3(4, 6), 256>>>(feats, Wd, bd);

    // span composition: 7 sequential iterations
    for (int sl = 1; sl <= 7; sl++) {
        int M = L - sl;
        sgemm_dual<<<dim3(16, 6), 256>>>(Wl, Wr, Gl, Gr, bl, br, bgl, bgr, sl);
        gate_kernel<<<(M * D + 255) / 256, 256>>>(sl);
    }

    // tag scores on all diagonals + gather
    init_xs<<<(L * NT * SPAN + 255) / 256, 256>>>();
    tagsc_kernel<<<L, 256>>>(Wt, bt);

    // gold + forward scan + final output
    forward_kernel<<<1, 32>>>(trans, bt, tags, out);
}

// round 2
// speedup vs baseline: 2.6612x; 2.6612x over previous
#include <cuda_runtime.h>
#include <cstdint>

#define L    768
#define D    256
#define NT   12
#define SPAN 8

// ---------------- device scratch (static, no allocs) ----------------
__device__ __align__(16) float g_ht[8][L * D];        // ht per span-length diagonal
__device__ __align__(16) float g_z[L * 4 * D];        // z buffer (1024 cols)
__device__ __align__(16) float g_tagsc[8][L * NT];    // tag scores per diagonal (for gold)
__device__ __align__(16) float g_ex[L * NT * SPAN];   // exp(span scores) [i][t2][k]

#define F2U(x) __float_as_uint(x)

__device__ __forceinline__ void mma_tf32(float& c0, float& c1, float& c2, float& c3,
                                         uint32_t a0, uint32_t a1, uint32_t a2, uint32_t a3,
                                         uint32_t b0, uint32_t b1)
{
    asm volatile("mma.sync.aligned.m16n8k8.row.col.f32.tf32.tf32.f32 "
                 "{%0,%1,%2,%3}, {%4,%5,%6,%7}, {%8,%9}, {%0,%1,%2,%3};\n"
                 : "+f"(c0), "+f"(c1), "+f"(c2), "+f"(c3)
                 : "r"(a0), "r"(a1), "r"(a2), "r"(a3), "r"(b0), "r"(b1));
}

// ---------------- h = feats @ Wd^T + bd  (tf32 MMA) ----------------
// M=768, N=256, K=512. BM=64, BN=64, BK=16, 128 threads (2x2 warps, warp tile 32x32).
__global__ void __launch_bounds__(128) sgemm_h_tf32(const float* __restrict__ A,
                                                    const float* __restrict__ B,
                                                    const float* __restrict__ bias)
{
    __shared__ __align__(16) float As[64 * 20];
    __shared__ __align__(16) float Bs[64 * 20];
    const int K = 512;
    const int tid = threadIdx.x;
    const int lane = tid & 31, warp = tid >> 5;
    const int g = lane >> 2, c = lane & 3;
    const int wm = warp >> 1, wn = warp & 1;
    const int m0 = blockIdx.y * 64, n0 = blockIdx.x * 64;

    float acc[2][4][4] = {};

    for (int k0 = 0; k0 < K; k0 += 16) {
        __syncthreads();
        {
            int r0 = tid >> 2, c4 = (tid & 3) * 4;
            *(float4*)&As[r0 * 20 + c4] = *(const float4*)&A[(size_t)(m0 + r0) * K + k0 + c4];
            int r1 = r0 + 32;
            *(float4*)&As[r1 * 20 + c4] = *(const float4*)&A[(size_t)(m0 + r1) * K + k0 + c4];
            *(float4*)&Bs[r0 * 20 + c4] = *(const float4*)&B[(size_t)(n0 + r0) * K + k0 + c4];
            *(float4*)&Bs[r1 * 20 + c4] = *(const float4*)&B[(size_t)(n0 + r1) * K + k0 + c4];
        }
        __syncthreads();
#pragma unroll
        for (int kc = 0; kc < 2; kc++) {
            const int ko = kc * 8 + c;
            uint32_t af[2][4];
#pragma unroll
            for (int mi = 0; mi < 2; mi++) {
                const float* p = &As[(wm * 32 + mi * 16 + g) * 20 + ko];
                af[mi][0] = F2U(p[0]);        af[mi][2] = F2U(p[4]);
                af[mi][1] = F2U(p[8 * 20]);   af[mi][3] = F2U(p[8 * 20 + 4]);
            }
#pragma unroll
            for (int ni = 0; ni < 4; ni++) {
                const float* pb = &Bs[(wn * 32 + ni * 8 + g) * 20 + ko];
                uint32_t b0 = F2U(pb[0]), b1 = F2U(pb[4]);
#pragma unroll
                for (int mi = 0; mi < 2; mi++)
                    mma_tf32(acc[mi][ni][0], acc[mi][ni][1], acc[mi][ni][2], acc[mi][ni][3],
                             af[mi][0], af[mi][1], af[mi][2], af[mi][3], b0, b1);
            }
        }
    }
#pragma unroll
    for (int ni = 0; ni < 4; ni++) {
        int col = n0 + wn * 32 + ni * 8 + 2 * c;
        float bv0 = bias[col], bv1 = bias[col + 1];
#pragma unroll
        for (int mi = 0; mi < 2; mi++) {
            int row = m0 + wm * 32 + mi * 16 + g;
            g_ht[0][(size_t)row * 256 + col]           = acc[mi][ni][0] + bv0;
            g_ht[0][(size_t)row * 256 + col + 1]       = acc[mi][ni][1] + bv1;
            g_ht[0][(size_t)(row + 8) * 256 + col]     = acc[mi][ni][2] + bv0;
            g_ht[0][(size_t)(row + 8) * 256 + col + 1] = acc[mi][ni][3] + bv1;
        }
    }
}

// ---------------- dual GEMM: z = l@WL^T + r@WR^T + bias  (tf32 MMA) ----------------
// l = ht_prev[m], r = ht_prev[m+1]; N=1024 (cols<256 -> Wl/Wr, else Gl/Gr). K=256.
// BM=64(+1 shift row), BN=64, BK=16, 128 threads. Grid (16, 12) = 192 CTAs.
__global__ void __launch_bounds__(128) sgemm_dual_tf32(
    const float* __restrict__ Wl, const float* __restrict__ Wr,
    const float* __restrict__ Gl, const float* __restrict__ Gr,
    const float* __restrict__ bl, const float* __restrict__ br,
    const float* __restrict__ bgl, const float* __restrict__ bgr,
    int sl)
{
    const int M = L - sl;
    const float* Aht = g_ht[sl - 1];
    __shared__ __align__(16) float As[65 * 20];
    __shared__ __align__(16) float BsL[64 * 20];
    __shared__ __align__(16) float BsR[64 * 20];
    const int tid = threadIdx.x;
    const int lane = tid & 31, warp = tid >> 5;
    const int g = lane >> 2, c = lane & 3;
    const int wm = warp >> 1, wn = warp & 1;
    const int m0 = blockIdx.y * 64, n0 = blockIdx.x * 64;
    const float* BLg = (n0 < 256) ? (Wl + (size_t)n0 * 256) : (Gl + (size_t)(n0 - 256) * 256);
    const float* BRg = (n0 < 256) ? (Wr + (size_t)n0 * 256) : (Gr + (size_t)(n0 - 256) * 256);

    float acc[2][4][4] = {};

    for (int k0 = 0; k0 < 256; k0 += 16) {
        __syncthreads();
        // A tile: 65 rows x 16 cols = 260 float4
        for (int idx = tid; idx < 260; idx += 128) {
            int r = idx >> 2, c4 = (idx & 3) * 4;
            *(float4*)&As[r * 20 + c4] = *(const float4*)&Aht[(size_t)(m0 + r) * 256 + k0 + c4];
        }
        {
            int r0 = tid >> 2, c4 = (tid & 3) * 4;
            *(float4*)&BsL[r0 * 20 + c4] = *(const float4*)&BLg[(size_t)r0 * 256 + k0 + c4];
            *(float4*)&BsR[r0 * 20 + c4] = *(const float4*)&BRg[(size_t)r0 * 256 + k0 + c4];
            int r1 = r0 + 32;
            *(float4*)&BsL[r1 * 20 + c4] = *(const float4*)&BLg[(size_t)r1 * 256 + k0 + c4];
            *(float4*)&BsR[r1 * 20 + c4] = *(const float4*)&BRg[(size_t)r1 * 256 + k0 + c4];
        }
        __syncthreads();
#pragma unroll
        for (int kc = 0; kc < 2; kc++) {
            const int ko = kc * 8 + c;
            uint32_t al[2][4], ar[2][4];
#pragma unroll
            for (int mi = 0; mi < 2; mi++) {
                const float* p = &As[(wm * 32 + mi * 16 + g) * 20 + ko];
                al[mi][0] = F2U(p[0]);        al[mi][2] = F2U(p[4]);
                al[mi][1] = F2U(p[8 * 20]);   al[mi][3] = F2U(p[8 * 20 + 4]);
                const float* q = p + 20;      // shifted by one row: r operand
                ar[mi][0] = F2U(q[0]);        ar[mi][2] = F2U(q[4]);
                ar[mi][1] = F2U(q[8 * 20]);   ar[mi][3] = F2U(q[8 * 20 + 4]);
            }
#pragma unroll
            for (int ni = 0; ni < 4; ni++) {
                const float* pl = &BsL[(wn * 32 + ni * 8 + g) * 20 + ko];
                uint32_t b0 = F2U(pl[0]), b1 = F2U(pl[4]);
                const float* pr = &BsR[(wn * 32 + ni * 8 + g) * 20 + ko];
                uint32_t d0 = F2U(pr[0]), d1 = F2U(pr[4]);
#pragma unroll
                for (int mi = 0; mi < 2; mi++) {
                    mma_tf32(acc[mi][ni][0], acc[mi][ni][1], acc[mi][ni][2], acc[mi][ni][3],
                             al[mi][0], al[mi][1], al[mi][2], al[mi][3], b0, b1);
                    mma_tf32(acc[mi][ni][0], acc[mi][ni][1], acc[mi][ni][2], acc[mi][ni][3],
                             ar[mi][0], ar[mi][1], ar[mi][2], ar[mi][3], d0, d1);
                }
            }
        }
    }
    // epilogue: + (bl+br | bgl+bgr), masked store rows < M
#pragma unroll
    for (int ni = 0; ni < 4; ni++) {
        int col = n0 + wn * 32 + ni * 8 + 2 * c;
        float bv0, bv1;
        if (col < 256) { bv0 = bl[col] + br[col];           bv1 = bl[col + 1] + br[col + 1]; }
        else           { bv0 = bgl[col - 256] + bgr[col - 256]; bv1 = bgl[col - 255] + bgr[col - 255]; }
#pragma unroll
        for (int mi = 0; mi < 2; mi++) {
            int row0 = m0 + wm * 32 + mi * 16 + g;
            if (row0 < M) {
                g_z[(size_t)row0 * 1024 + col]     = acc[mi][ni][0] + bv0;
                g_z[(size_t)row0 * 1024 + col + 1] = acc[mi][ni][1] + bv1;
            }
            int row1 = row0 + 8;
            if (row1 < M) {
                g_z[(size_t)row1 * 1024 + col]     = acc[mi][ni][2] + bv0;
                g_z[(size_t)row1 * 1024 + col + 1] = acc[mi][ni][3] + bv1;
            }
        }
    }
}

// ---------------- gate epilogue: ht_sl = w0*h_hat + w1*l + w2*r ----------------
__global__ void gate_kernel(int sl)
{
    const int M = L - sl;
    int idx = blockIdx.x * 256 + threadIdx.x;
    if (idx >= M * D) return;
    int pos = idx >> 8;
    int d = idx & 255;
    const float* zp = g_z + (size_t)pos * 1024;
    float hv = zp[d];
    float g0 = zp[256 + d], g1 = zp[512 + d], g2 = zp[768 + d];
    float hh = 4.f / (1.f + __expf(-hv)) - 2.f;
    float mx = fmaxf(g0, fmaxf(g1, g2));
    float e0 = __expf(g0 - mx), e1 = __expf(g1 - mx), e2 = __expf(g2 - mx);
    float inv = 1.f / (e0 + e1 + e2);
    float lft = g_ht[sl - 1][idx];
    float rgt = g_ht[sl - 1][idx + D];
    g_ht[sl][idx] = (e0 * hh + e1 * lft + e2 * rgt) * inv;
}

// ---------------- tag scores + exp-gather into ex layout ----------------
// warp per (sl,pos): val = ht_sl[pos]·Wt[t] + bt[t]; writes g_tagsc and g_ex=exp(val).
__global__ void tagsc_kernel(const float* __restrict__ Wt, const float* __restrict__ bt)
{
    __shared__ float sWt[NT * D];
    int tid = threadIdx.x;
    for (int i = tid; i < NT * D; i += 256) sWt[i] = Wt[i];
    __syncthreads();
    int warp = tid >> 5, lane = tid & 31;
    int gw = blockIdx.x * 8 + warp;        // 0..6143
    int sl = gw / L;
    int pos = gw - sl * L;
    if (pos + sl >= L) return;
    const float* hp = g_ht[sl] + (size_t)pos * D;
    float4 h0 = *(const float4*)&hp[lane * 8];
    float4 h1 = *(const float4*)&hp[lane * 8 + 4];
    float hv[8] = {h0.x,h0.y,h0.z,h0.w,h1.x,h1.y,h1.z,h1.w};
    int i_end = pos + sl, k = 7 - sl;
#pragma unroll
    for (int t = 0; t < NT; t++) {
        const float* wp = &sWt[t * D + lane * 8];
        float4 w0 = *(const float4*)wp;
        float4 w1 = *(const float4*)(wp + 4);
        float s = hv[0]*w0.x + hv[1]*w0.y + hv[2]*w0.z + hv[3]*w0.w
                + hv[4]*w1.x + hv[5]*w1.y + hv[6]*w1.z + hv[7]*w1.w;
#pragma unroll
        for (int o = 16; o; o >>= 1) s += __shfl_xor_sync(0xffffffffu, s, o);
        if (lane == 0) {
            float val = s + bt[t];
            g_tagsc[sl][pos * NT + t] = val;
            g_ex[((size_t)i_end * NT + t) * SPAN + k] = __expf(val);
        }
    }
}

// ---------------- gold score + exp-domain forward scan (single warp) ----------------
// B[k] = exp(beta - S) register ring; per step: v = sum_k ex*B (8 FMA),
// B' = sum_t1 Texp[t1]*shfl(v,t1) (12 shfl+FMA). Rescale by v[0] every 8 steps.
__global__ void forward_kernel(const float* __restrict__ trans,
                               const float* __restrict__ bt,
                               const int* __restrict__ tags,
                               float* __restrict__ out)
{
    const int lane = threadIdx.x;

    // ---- gold score (96 spans) ----
    float gold = 0.f;
    for (int s = lane; s < 96; s += 32) {
        int i  = tags[s * 4 + 0];
        int j  = tags[s * 4 + 1];
        int pr = tags[s * 4 + 2];
        int t  = tags[s * 4 + 3];
        int sl = j - i;
        float base;
        if (sl >= 0 && sl < SPAN && i >= 0 && i + sl < L)
            base = g_tagsc[sl][i * NT + t];
        else
            base = bt[t];                  // zero-score region: tagsc = bt
        gold += base + trans[pr * NT + t];
    }
#pragma unroll
    for (int o = 16; o; o >>= 1) gold += __shfl_xor_sync(0xffffffffu, gold, o);

    // ---- zero never-written ex slots (i<7, k<7-i) ----
    for (int idx = lane; idx < 7 * NT * SPAN; idx += 32) {
        int i = idx / (NT * SPAN);
        int rem = idx - i * (NT * SPAN);
        int t = rem >> 3, k = rem & 7;
        if (k < 7 - i) g_ex[((size_t)i * NT + t) * SPAN + k] = 0.f;
    }
    __syncwarp();

    // ---- setup ----
    const int t2 = lane < NT ? lane : NT - 1;
    float Texp[NT];
#pragma unroll
    for (int t1 = 0; t1 < NT; t1++) Texp[t1] = expf(trans[t1 * NT + t2]);
    // exp(beta_{-1}) = Texp[START=10] (other alphaInit terms underflow to 0, like ref)
    float B[8] = {0.f, 0.f, 0.f, 0.f, 0.f, 0.f, 0.f, Texp[10]};
    float S = 0.f;

    const float4* exbase = (const float4*)(g_ex + (size_t)t2 * SPAN);
    // per-step stride in float4: NT*SPAN/4 = 24
    float4 curA[8], curB[8], nxtA[8], nxtB[8];
#pragma unroll
    for (int u = 0; u < 8; u++) {          // preload block 0
        curA[u] = exbase[(size_t)u * 24];
        curB[u] = exbase[(size_t)u * 24 + 1];
    }

    float v = 0.f;
    for (int b = 0; b < 96; b++) {
        if (b < 95) {
            const float4* nb = exbase + (size_t)(b + 1) * 8 * 24;
#pragma unroll
            for (int u = 0; u < 8; u++) {
                nxtA[u] = nb[(size_t)u * 24];
                nxtB[u] = nb[(size_t)u * 24 + 1];
            }
        }
#pragma unroll
        for (int u = 0; u < 8; u++) {
            float e0 = curA[u].x, e1 = curA[u].y, e2 = curA[u].z, e3 = curA[u].w;
            float e4 = curB[u].x, e5 = curB[u].y, e6 = curB[u].z, e7 = curB[u].w;
            // slot for x-index k is (u+k)&7 ; tree-reduce
            float v01 = fmaf(e1, B[(u + 1) & 7], e0 * B[(u + 0) & 7]);
            float v23 = fmaf(e3, B[(u + 3) & 7], e2 * B[(u + 2) & 7]);
            float v45 = fmaf(e5, B[(u + 5) & 7], e4 * B[(u + 4) & 7]);
            float v67 = fmaf(e7, B[(u + 7) & 7], e6 * B[(u + 6) & 7]);
            v = (v01 + v23) + (v45 + v67);
            // B'[t2] = sum_t1 Texp[t1] * v[t1]  (two parallel half-chains)
            float bnA = 0.f, bnB = 0.f;
#pragma unroll
            for (int t1 = 0; t1 < 6; t1++) {
                bnA = fmaf(Texp[t1],     __shfl_sync(0xffffffffu, v, t1),     bnA);
                bnB = fmaf(Texp[t1 + 6], __shfl_sync(0xffffffffu, v, t1 + 6), bnB);
            }
            B[u] = bnA + bnB;              // slot i&7 = u
        }
        if (b < 95) {
            float cc = __shfl_sync(0xffffffffu, v, 0);
            float inv = 1.f / cc;
#pragma unroll
            for (int k = 0; k < 8; k++) B[k] *= inv;
            S += logf(cc);
#pragma unroll
            for (int u = 0; u < 8; u++) { curA[u] = nxtA[u]; curB[u] = nxtB[u]; }
        }
    }

    // alpha_{L-1}[t2] = S + log(v) ; logZ = sum over t2 = 0..10
    float contrib = (lane < 11) ? (S + logf(v)) : 0.f;
#pragma unroll
    for (int o = 16; o; o >>= 1) contrib += __shfl_xor_sync(0xffffffffu, contrib, o);
    if (lane == 0) out[0] = contrib - gold;
}

// ---------------- launch ----------------
extern "C" void kernel_launch(void* const* d_in, const int* in_sizes, int n_in,
                              void* d_out, int out_size)
{
    const float* feats = (const float*)d_in[0];
    const int*   tags  = (const int*)d_in[1];
    const float* Wd    = (const float*)d_in[2];
    const float* bd    = (const float*)d_in[3];
    const float* Wl    = (const float*)d_in[4];
    const float* bl    = (const float*)d_in[5];
    const float* Wr    = (const float*)d_in[6];
    const float* br    = (const float*)d_in[7];
    const float* Gl    = (const float*)d_in[8];
    const float* bgl   = (const float*)d_in[9];
    const float* Gr    = (const float*)d_in[10];
    const float* bgr   = (const float*)d_in[11];
    const float* Wt    = (const float*)d_in[12];
    const float* bt    = (const float*)d_in[13];
    const float* trans = (const float*)d_in[14];
    float* out = (float*)d_out;

    // h = feats @ Wd^T + bd   (grid: N/64 x M/64)
    sgemm_h_tf32<<<dim3(4, 12), 128>>>(feats, Wd, bd);

    // span composition: 7 sequential iterations
    for (int sl = 1; sl <= 7; sl++) {
        int M = L - sl;
        sgemm_dual_tf32<<<dim3(16, 12), 128>>>(Wl, Wr, Gl, Gr, bl, br, bgl, bgr, sl);
        gate_kernel<<<(M * D + 255) / 256, 256>>>(sl);
    }

    // tag scores + exp gather on all diagonals
    tagsc_kernel<<<L, 256>>>(Wt, bt);

    // gold + exp-domain forward scan
    forward_kernel<<<1, 32>>>(trans, bt, tags, out);
}